// round 2
// baseline (speedup 1.0000x reference)
#include <cuda_runtime.h>
#include <cuda_bf16.h>
#include <float.h>
#include <math.h>

#define B_SEG 16
#define INC 128
#define HID 32

// Scratch (no allocations allowed)
__device__ float    g_sum [B_SEG * INC];
__device__ unsigned g_maxk[B_SEG * INC];
__device__ int      g_cnt [B_SEG];
__device__ float    g_gate[B_SEG * INC];

// Monotone float <-> unsigned key for atomicMax
__device__ __forceinline__ unsigned orderFloat(float f) {
    unsigned u = __float_as_uint(f);
    return (u & 0x80000000u) ? ~u : (u | 0x80000000u);
}
__device__ __forceinline__ float unorderFloat(unsigned k) {
    return (k & 0x80000000u) ? __uint_as_float(k & 0x7fffffffu)
                             : __uint_as_float(~k);
}

__global__ void init_kernel() {
    int t = threadIdx.x;
    for (int i = t; i < B_SEG * INC; i += blockDim.x) {
        g_sum[i]  = 0.0f;
        g_maxk[i] = 0u;   // key 0 < key(any real float)
    }
    if (t < B_SEG) g_cnt[t] = 0;
}

__device__ __forceinline__ void flush_acc(int seg, int c4,
                                          const float4& s, const float4& m) {
    if (seg < 0) return;
    float*    sp = &g_sum [seg * INC + c4 * 4];
    unsigned* mp = &g_maxk[seg * INC + c4 * 4];
    atomicAdd(sp + 0, s.x); atomicAdd(sp + 1, s.y);
    atomicAdd(sp + 2, s.z); atomicAdd(sp + 3, s.w);
    atomicMax(mp + 0, orderFloat(m.x)); atomicMax(mp + 1, orderFloat(m.y));
    atomicMax(mp + 2, orderFloat(m.z)); atomicMax(mp + 3, orderFloat(m.w));
}

// 256 threads: 8 rows/warp-slice, unrolled x4 -> 32 rows per block iter.
// All loads for the 4 rows are issued before any accumulate (MLP=4+).
__global__ void reduce_kernel(const float4* __restrict__ f,
                              const int*    __restrict__ bidx,
                              int n_rows, int rows_per_block) {
    int t      = threadIdx.x;
    int rowoff = t >> 5;
    int c4     = t & 31;
    int r0 = blockIdx.x * rows_per_block;
    int r1 = min(r0 + rows_per_block, n_rows);

    __shared__ int cnt_s[B_SEG];
    if (t < B_SEG) cnt_s[t] = 0;
    __syncthreads();

    float4 sum = make_float4(0.f, 0.f, 0.f, 0.f);
    float4 mx  = make_float4(-FLT_MAX, -FLT_MAX, -FLT_MAX, -FLT_MAX);
    int cur = -1;

    for (int r = r0 + rowoff; r < r1; r += 32) {
        int ra = r, rb = r + 8, rc = r + 16, rd = r + 24;
        bool ga = ra < r1, gb = rb < r1, gc = rc < r1, gd = rd < r1;

        // ---- front-batched loads ----
        int s0 = 0, s1 = 0, s2 = 0, s3 = 0;
        float4 v0, v1, v2, v3;
        if (ga) { s0 = __ldg(&bidx[ra]); v0 = __ldg(&f[(size_t)ra * 32 + c4]); }
        if (gb) { s1 = __ldg(&bidx[rb]); v1 = __ldg(&f[(size_t)rb * 32 + c4]); }
        if (gc) { s2 = __ldg(&bidx[rc]); v2 = __ldg(&f[(size_t)rc * 32 + c4]); }
        if (gd) { s3 = __ldg(&bidx[rd]); v3 = __ldg(&f[(size_t)rd * 32 + c4]); }

        // ---- accumulate ----
        if (ga) {
            if (s0 != cur) {
                flush_acc(cur, c4, sum, mx);
                cur = s0;
                sum = make_float4(0.f, 0.f, 0.f, 0.f);
                mx  = make_float4(-FLT_MAX, -FLT_MAX, -FLT_MAX, -FLT_MAX);
            }
            sum.x += v0.x; sum.y += v0.y; sum.z += v0.z; sum.w += v0.w;
            mx.x = fmaxf(mx.x, v0.x); mx.y = fmaxf(mx.y, v0.y);
            mx.z = fmaxf(mx.z, v0.z); mx.w = fmaxf(mx.w, v0.w);
            if (c4 == 0) atomicAdd(&cnt_s[s0], 1);
        }
        if (gb) {
            if (s1 != cur) {
                flush_acc(cur, c4, sum, mx);
                cur = s1;
                sum = make_float4(0.f, 0.f, 0.f, 0.f);
                mx  = make_float4(-FLT_MAX, -FLT_MAX, -FLT_MAX, -FLT_MAX);
            }
            sum.x += v1.x; sum.y += v1.y; sum.z += v1.z; sum.w += v1.w;
            mx.x = fmaxf(mx.x, v1.x); mx.y = fmaxf(mx.y, v1.y);
            mx.z = fmaxf(mx.z, v1.z); mx.w = fmaxf(mx.w, v1.w);
            if (c4 == 0) atomicAdd(&cnt_s[s1], 1);
        }
        if (gc) {
            if (s2 != cur) {
                flush_acc(cur, c4, sum, mx);
                cur = s2;
                sum = make_float4(0.f, 0.f, 0.f, 0.f);
                mx  = make_float4(-FLT_MAX, -FLT_MAX, -FLT_MAX, -FLT_MAX);
            }
            sum.x += v2.x; sum.y += v2.y; sum.z += v2.z; sum.w += v2.w;
            mx.x = fmaxf(mx.x, v2.x); mx.y = fmaxf(mx.y, v2.y);
            mx.z = fmaxf(mx.z, v2.z); mx.w = fmaxf(mx.w, v2.w);
            if (c4 == 0) atomicAdd(&cnt_s[s2], 1);
        }
        if (gd) {
            if (s3 != cur) {
                flush_acc(cur, c4, sum, mx);
                cur = s3;
                sum = make_float4(0.f, 0.f, 0.f, 0.f);
                mx  = make_float4(-FLT_MAX, -FLT_MAX, -FLT_MAX, -FLT_MAX);
            }
            sum.x += v3.x; sum.y += v3.y; sum.z += v3.z; sum.w += v3.w;
            mx.x = fmaxf(mx.x, v3.x); mx.y = fmaxf(mx.y, v3.y);
            mx.z = fmaxf(mx.z, v3.z); mx.w = fmaxf(mx.w, v3.w);
            if (c4 == 0) atomicAdd(&cnt_s[s3], 1);
        }
    }
    flush_acc(cur, c4, sum, mx);

    __syncthreads();
    if (t < B_SEG && cnt_s[t] > 0) atomicAdd(&g_cnt[t], cnt_s[t]);
}

// One block, 512 threads = 16 warps (one warp per segment, lane = hidden unit).
__global__ void gate_kernel(const float* __restrict__ W1,
                            const float* __restrict__ b1,
                            const float* __restrict__ W2,
                            const float* __restrict__ b2) {
    __shared__ float W1s[INC * HID];          // 16 KB, layout [c][h] (as given)
    __shared__ float mean_s[B_SEG * INC];     // 8 KB
    __shared__ float max_s [B_SEG * INC];     // 8 KB
    __shared__ float hidm[B_SEG * HID];       // 2 KB
    __shared__ float hidx[B_SEG * HID];       // 2 KB

    int tid = threadIdx.x;

    for (int i = tid; i < INC * HID; i += blockDim.x) W1s[i] = W1[i];
    for (int i = tid; i < B_SEG * INC; i += blockDim.x) {
        int b = i >> 7;
        int cnt = g_cnt[b];
        float inv = 1.0f / fmaxf((float)cnt, 1.0f);
        mean_s[i] = g_sum[i] * inv;
        max_s[i]  = (cnt > 0) ? unorderFloat(g_maxk[i]) : 0.0f;
    }
    __syncthreads();

    int b = tid >> 5;   // segment (16 warps)
    int h = tid & 31;   // hidden unit
    float am = b1[h], ax = b1[h];
    #pragma unroll 8
    for (int c = 0; c < INC; c++) {
        float w = W1s[c * HID + h];
        am = fmaf(mean_s[b * INC + c], w, am);
        ax = fmaf(max_s [b * INC + c], w, ax);
    }
    hidm[b * HID + h] = fmaxf(am, 0.0f);
    hidx[b * HID + h] = fmaxf(ax, 0.0f);
    __syncthreads();

    // 2048 outputs, 512 threads x 4
    #pragma unroll
    for (int k = 0; k < 4; k++) {
        int idx = tid + k * 512;
        int bb = idx >> 7;
        int c  = idx & 127;
        float om = b2[c], ox = b2[c];
        #pragma unroll 8
        for (int hh = 0; hh < HID; hh++) {
            float w = __ldg(&W2[hh * INC + c]);
            om = fmaf(hidm[bb * HID + hh], w, om);
            ox = fmaf(hidx[bb * HID + hh], w, ox);
        }
        float z = om + ox;
        g_gate[idx] = 1.0f / (1.0f + __expf(-z));
    }
}

// Streaming scale: out = feats * gate[batch_idx]. 4-way batched loads.
__global__ void scale_kernel(const float4* __restrict__ f,
                             const int*    __restrict__ bidx,
                             float4* __restrict__ out,
                             size_t nvec) {
    size_t base   = (size_t)blockIdx.x * blockDim.x + threadIdx.x;
    size_t stride = (size_t)gridDim.x * blockDim.x;
    const float4* gate4 = (const float4*)g_gate;

    size_t i0 = base;
    size_t i1 = base + stride;
    size_t i2 = base + 2 * stride;
    size_t i3 = base + 3 * stride;

    float4 v0, v1, v2, v3;
    int s0 = 0, s1 = 0, s2 = 0, s3 = 0;
    if (i0 < nvec) { v0 = __ldg(&f[i0]); s0 = __ldg(&bidx[i0 >> 5]); }
    if (i1 < nvec) { v1 = __ldg(&f[i1]); s1 = __ldg(&bidx[i1 >> 5]); }
    if (i2 < nvec) { v2 = __ldg(&f[i2]); s2 = __ldg(&bidx[i2 >> 5]); }
    if (i3 < nvec) { v3 = __ldg(&f[i3]); s3 = __ldg(&bidx[i3 >> 5]); }

    if (i0 < nvec) {
        float4 g = gate4[s0 * 32 + (i0 & 31)];
        v0.x *= g.x; v0.y *= g.y; v0.z *= g.z; v0.w *= g.w;
        out[i0] = v0;
    }
    if (i1 < nvec) {
        float4 g = gate4[s1 * 32 + (i1 & 31)];
        v1.x *= g.x; v1.y *= g.y; v1.z *= g.z; v1.w *= g.w;
        out[i1] = v1;
    }
    if (i2 < nvec) {
        float4 g = gate4[s2 * 32 + (i2 & 31)];
        v2.x *= g.x; v2.y *= g.y; v2.z *= g.z; v2.w *= g.w;
        out[i2] = v2;
    }
    if (i3 < nvec) {
        float4 g = gate4[s3 * 32 + (i3 & 31)];
        v3.x *= g.x; v3.y *= g.y; v3.z *= g.z; v3.w *= g.w;
        out[i3] = v3;
    }
}

extern "C" void kernel_launch(void* const* d_in, const int* in_sizes, int n_in,
                              void* d_out, int out_size) {
    const float* feats = (const float*)d_in[0];
    const int*   bidx  = (const int*)d_in[1];
    const float* W1    = (const float*)d_in[2];
    const float* b1    = (const float*)d_in[3];
    const float* W2    = (const float*)d_in[4];
    const float* b2    = (const float*)d_in[5];
    float* out = (float*)d_out;

    int n_rows = in_sizes[1];                   // N points
    size_t nvec = (size_t)n_rows * (INC / 4);   // float4 count

    init_kernel<<<1, 256>>>();

    int red_blocks = 2048;
    int rows_per_block = (n_rows + red_blocks - 1) / red_blocks;
    reduce_kernel<<<red_blocks, 256>>>((const float4*)feats, bidx,
                                       n_rows, rows_per_block);

    gate_kernel<<<1, 512>>>(W1, b1, W2, b2);

    int sthreads = 256;
    size_t per_launch = (size_t)sthreads * 4;
    int sblocks = (int)((nvec + per_launch - 1) / per_launch);
    scale_kernel<<<sblocks, sthreads>>>((const float4*)feats, bidx,
                                        (float4*)out, nvec);
}

// round 4
// speedup vs baseline: 1.3540x; 1.3540x over previous
#include <cuda_runtime.h>
#include <cuda_bf16.h>
#include <float.h>
#include <math.h>

#define B_SEG 16
#define INC 128
#define HID 32

// Scratch (no allocations allowed)
__device__ float    g_sum [B_SEG * INC];
__device__ unsigned g_maxk[B_SEG * INC];
__device__ int      g_off [B_SEG + 1];
__device__ float    g_gate[B_SEG * INC];

// Monotone float <-> unsigned key for atomicMax
__device__ __forceinline__ unsigned orderFloat(float f) {
    unsigned u = __float_as_uint(f);
    return (u & 0x80000000u) ? ~u : (u | 0x80000000u);
}
__device__ __forceinline__ float unorderFloat(unsigned k) {
    return (k & 0x80000000u) ? __uint_as_float(k & 0x7fffffffu)
                             : __uint_as_float(~k);
}

// Init accumulators + binary-search segment boundaries (bidx is sorted).
__global__ void prep_kernel(const int* __restrict__ bidx, int n) {
    int t = threadIdx.x;
    for (int i = t; i < B_SEG * INC; i += blockDim.x) {
        g_sum[i]  = 0.0f;
        g_maxk[i] = 0u;
    }
    if (t <= B_SEG) {
        int lo = 0, hi = n;             // lower_bound of value t
        while (lo < hi) {
            int mid = (lo + hi) >> 1;
            if (__ldg(&bidx[mid]) < t) lo = mid + 1; else hi = mid;
        }
        g_off[t] = lo;
    }
}

// Reduce: contiguous chunk per block; segment bounds from g_off (no bidx
// loads, no per-row branches). Block-level smem reduction before atomics.
__global__ void reduce_kernel(const float4* __restrict__ f,
                              int n_rows, int rows_per_block) {
    int t      = threadIdx.x;
    int rowoff = t >> 5;            // warp id (0..7)
    int c4     = t & 31;            // float4 lane within row
    int r0 = blockIdx.x * rows_per_block;
    int r1 = min(r0 + rows_per_block, n_rows);
    if (r0 >= n_rows) return;

    __shared__ int    off_s[B_SEG + 1];
    __shared__ float4 sum_s[8 * 32];   // [warp][c4]  4 KB
    __shared__ float4 max_s4[8 * 32];  // [warp][c4]  4 KB
    if (t <= B_SEG) off_s[t] = g_off[t];
    __syncthreads();

    for (int b = 0; b < B_SEG; b++) {
        int a = max(r0, off_s[b]);
        int e = min(r1, off_s[b + 1]);
        if (a >= e) continue;

        float4 sum = make_float4(0.f, 0.f, 0.f, 0.f);
        float4 mx  = make_float4(-FLT_MAX, -FLT_MAX, -FLT_MAX, -FLT_MAX);

        int r = a + rowoff;
        // main: 4 unguarded 128b loads per iter (front-batched, MLP>=4)
        for (; r + 24 < e; r += 32) {
            const float4* p = &f[(size_t)r * 32 + c4];
            float4 v0 = __ldg(p);
            float4 v1 = __ldg(p +  8 * 32);
            float4 v2 = __ldg(p + 16 * 32);
            float4 v3 = __ldg(p + 24 * 32);
            sum.x += v0.x + v1.x + v2.x + v3.x;
            sum.y += v0.y + v1.y + v2.y + v3.y;
            sum.z += v0.z + v1.z + v2.z + v3.z;
            sum.w += v0.w + v1.w + v2.w + v3.w;
            mx.x = fmaxf(mx.x, fmaxf(fmaxf(v0.x, v1.x), fmaxf(v2.x, v3.x)));
            mx.y = fmaxf(mx.y, fmaxf(fmaxf(v0.y, v1.y), fmaxf(v2.y, v3.y)));
            mx.z = fmaxf(mx.z, fmaxf(fmaxf(v0.z, v1.z), fmaxf(v2.z, v3.z)));
            mx.w = fmaxf(mx.w, fmaxf(fmaxf(v0.w, v1.w), fmaxf(v2.w, v3.w)));
        }
        for (; r < e; r += 8) {
            float4 v = __ldg(&f[(size_t)r * 32 + c4]);
            sum.x += v.x; sum.y += v.y; sum.z += v.z; sum.w += v.w;
            mx.x = fmaxf(mx.x, v.x); mx.y = fmaxf(mx.y, v.y);
            mx.z = fmaxf(mx.z, v.z); mx.w = fmaxf(mx.w, v.w);
        }

        // block reduce (all 256 threads reach these barriers uniformly)
        __syncthreads();
        sum_s [rowoff * 32 + c4] = sum;
        max_s4[rowoff * 32 + c4] = mx;
        __syncthreads();
        if (t < INC) {
            const float* ss = (const float*)sum_s;   // [warp][128 floats]
            const float* ms = (const float*)max_s4;
            float s = ss[t], m = ms[t];
            #pragma unroll
            for (int w = 1; w < 8; w++) {
                s += ss[w * INC + t];
                m  = fmaxf(m, ms[w * INC + t]);
            }
            atomicAdd(&g_sum[b * INC + t], s);
            atomicMax(&g_maxk[b * INC + t], orderFloat(m));
        }
        __syncthreads();
    }
}

// One block, 512 threads = 16 warps (one warp per segment, lane = hidden unit).
__global__ void gate_kernel(const float* __restrict__ W1,
                            const float* __restrict__ b1,
                            const float* __restrict__ W2,
                            const float* __restrict__ b2) {
    __shared__ float W1s[INC * HID];          // 16 KB, layout [c][h]
    __shared__ float mean_s[B_SEG * INC];     // 8 KB
    __shared__ float max_s [B_SEG * INC];     // 8 KB
    __shared__ float hidm[B_SEG * HID];       // 2 KB
    __shared__ float hidx[B_SEG * HID];       // 2 KB

    int tid = threadIdx.x;

    for (int i = tid; i < INC * HID; i += blockDim.x) W1s[i] = W1[i];
    for (int i = tid; i < B_SEG * INC; i += blockDim.x) {
        int b = i >> 7;
        int cnt = g_off[b + 1] - g_off[b];
        float inv = 1.0f / fmaxf((float)cnt, 1.0f);
        mean_s[i] = g_sum[i] * inv;
        max_s[i]  = (cnt > 0) ? unorderFloat(g_maxk[i]) : 0.0f;
    }
    __syncthreads();

    int b = tid >> 5;   // segment (16 warps)
    int h = tid & 31;   // hidden unit
    float am = b1[h], ax = b1[h];
    #pragma unroll 8
    for (int c = 0; c < INC; c++) {
        float w = W1s[c * HID + h];
        am = fmaf(mean_s[b * INC + c], w, am);
        ax = fmaf(max_s [b * INC + c], w, ax);
    }
    hidm[b * HID + h] = fmaxf(am, 0.0f);
    hidx[b * HID + h] = fmaxf(ax, 0.0f);
    __syncthreads();

    #pragma unroll
    for (int k = 0; k < 4; k++) {
        int idx = tid + k * 512;
        int bb = idx >> 7;
        int c  = idx & 127;
        float om = b2[c], ox = b2[c];
        #pragma unroll 8
        for (int hh = 0; hh < HID; hh++) {
            float w = __ldg(&W2[hh * INC + c]);
            om = fmaf(hidm[bb * HID + hh], w, om);
            ox = fmaf(hidx[bb * HID + hh], w, ox);
        }
        float z = om + ox;
        g_gate[idx] = 1.0f / (1.0f + __expf(-z));
    }
}

// Streaming scale: out = feats * gate[batch_idx]. 4-way batched loads.
__global__ void scale_kernel(const float4* __restrict__ f,
                             const int*    __restrict__ bidx,
                             float4* __restrict__ out,
                             size_t nvec) {
    size_t base   = (size_t)blockIdx.x * blockDim.x + threadIdx.x;
    size_t stride = (size_t)gridDim.x * blockDim.x;
    const float4* gate4 = (const float4*)g_gate;

    size_t i0 = base;
    size_t i1 = base + stride;
    size_t i2 = base + 2 * stride;
    size_t i3 = base + 3 * stride;

    float4 v0, v1, v2, v3;
    int s0 = 0, s1 = 0, s2 = 0, s3 = 0;
    if (i0 < nvec) { v0 = __ldg(&f[i0]); s0 = __ldg(&bidx[i0 >> 5]); }
    if (i1 < nvec) { v1 = __ldg(&f[i1]); s1 = __ldg(&bidx[i1 >> 5]); }
    if (i2 < nvec) { v2 = __ldg(&f[i2]); s2 = __ldg(&bidx[i2 >> 5]); }
    if (i3 < nvec) { v3 = __ldg(&f[i3]); s3 = __ldg(&bidx[i3 >> 5]); }

    if (i0 < nvec) {
        float4 g = gate4[s0 * 32 + (i0 & 31)];
        v0.x *= g.x; v0.y *= g.y; v0.z *= g.z; v0.w *= g.w;
        out[i0] = v0;
    }
    if (i1 < nvec) {
        float4 g = gate4[s1 * 32 + (i1 & 31)];
        v1.x *= g.x; v1.y *= g.y; v1.z *= g.z; v1.w *= g.w;
        out[i1] = v1;
    }
    if (i2 < nvec) {
        float4 g = gate4[s2 * 32 + (i2 & 31)];
        v2.x *= g.x; v2.y *= g.y; v2.z *= g.z; v2.w *= g.w;
        out[i2] = v2;
    }
    if (i3 < nvec) {
        float4 g = gate4[s3 * 32 + (i3 & 31)];
        v3.x *= g.x; v3.y *= g.y; v3.z *= g.z; v3.w *= g.w;
        out[i3] = v3;
    }
}

extern "C" void kernel_launch(void* const* d_in, const int* in_sizes, int n_in,
                              void* d_out, int out_size) {
    const float* feats = (const float*)d_in[0];
    const int*   bidx  = (const int*)d_in[1];
    const float* W1    = (const float*)d_in[2];
    const float* b1    = (const float*)d_in[3];
    const float* W2    = (const float*)d_in[4];
    const float* b2    = (const float*)d_in[5];
    float* out = (float*)d_out;

    int n_rows = in_sizes[1];                   // N points
    size_t nvec = (size_t)n_rows * (INC / 4);   // float4 count

    prep_kernel<<<1, 64>>>(bidx, n_rows);

    int red_blocks = 2048;
    int rows_per_block = (n_rows + red_blocks - 1) / red_blocks;
    reduce_kernel<<<red_blocks, 256>>>((const float4*)feats,
                                       n_rows, rows_per_block);

    gate_kernel<<<1, 512>>>(W1, b1, W2, b2);

    int sthreads = 256;
    size_t per_launch = (size_t)sthreads * 4;
    int sblocks = (int)((nvec + per_launch - 1) / per_launch);
    scale_kernel<<<sblocks, sthreads>>>((const float4*)feats, bidx,
                                        (float4*)out, nvec);
}